// round 3
// baseline (speedup 1.0000x reference)
#include <cuda_runtime.h>
#include <cstdint>

#define N_NODES   100000
#define N_EDGES   1600000
#define N_ETYPES  3
#define IN_FEATS  128
#define HEADS     4
#define OUT_FEATS 16
#define HD        64
#define NEG_SLOPE 0.2f
#define SCAN_B    1024
#define NB        ((N_NODES + SCAN_B - 1) / SCAN_B)   // 98

// ---------------- device scratch (static globals; no allocation) -------------
__device__ float4 g_feat[N_NODES * 16];   // [N][64] as 16 x float4 (25.6 MB)
__device__ float4 g_el[N_NODES];          // [N][4]
__device__ float4 g_er[N_NODES];          // [N][4]
__device__ float4 g_ee[N_ETYPES];         // [3][4]
__device__ int    g_cnt[N_NODES];
__device__ int    g_incl[N_NODES];
__device__ int    g_bsum[NB];
__device__ int    g_boff[NB];
__device__ int    g_rowptr[N_NODES + 1];
__device__ int    g_cur[N_NODES];
__device__ int2   g_es[N_EDGES];          // sorted: {src, orig_id*4 | etype}

// ---------------- init: zero histogram ---------------------------------------
__global__ void k_init() {
    int i = blockIdx.x * 256 + threadIdx.x;
    if (i < N_NODES) g_cnt[i] = 0;
}

// ---------------- per-etype edge term ee[t][h] -------------------------------
__global__ void k_ee(const float* __restrict__ W_e, const float* __restrict__ attn_e,
                     const float* __restrict__ edge_emb) {
    int w = threadIdx.x >> 5, lane = threadIdx.x & 31;
    if (w >= N_ETYPES * HEADS) return;
    int t = w >> 2, h = w & 3;
    float acc = 0.0f;
#pragma unroll
    for (int ei = 0; ei < 2; ei++) {
        int e = lane + ei * 32;
        float dot = 0.0f;
#pragma unroll 8
        for (int k = 0; k < 64; k++)
            dot += edge_emb[t * 64 + k] * W_e[k * 256 + h * 64 + e];
        acc += dot * attn_e[h * 64 + e];
    }
#pragma unroll
    for (int o = 16; o; o >>= 1) acc += __shfl_xor_sync(0xffffffffu, acc, o);
    if (lane == 0) ((float*)g_ee)[t * 4 + h] = acc;
}

// ---------------- GEMM: feat = x @ W  (+ fused el/er epilogue) ---------------
// 128 rows x 64 cols per block, 256 threads, 8x4 microtile -> FMA-bound.
__global__ __launch_bounds__(256, 2) void k_gemm(const float* __restrict__ x,
                                                 const float* __restrict__ W,
                                                 const float* __restrict__ attn_l,
                                                 const float* __restrict__ attn_r) {
    __shared__ float As[32][132];   // transposed A tile, rows 16B-aligned
    __shared__ float Bs[32][64];
    int tid = threadIdx.x;
    int tx = tid & 15, ty = tid >> 4;   // tx: 4 cols, ty: 8 rows
    int rb = blockIdx.x * 128;
    float acc[8][4] = {};

    for (int k0 = 0; k0 < IN_FEATS; k0 += 32) {
#pragma unroll
        for (int i = 0; i < 4; i++) {
            int f   = tid + 256 * i;      // float4 slot 0..1023
            int row = f >> 3;             // 0..127
            int kq  = f & 7;              // k = kq*4
            float4 v = make_float4(0.f, 0.f, 0.f, 0.f);
            int gr = rb + row;
            if (gr < N_NODES) v = *(const float4*)&x[(long)gr * IN_FEATS + k0 + kq * 4];
            As[kq * 4 + 0][row] = v.x; As[kq * 4 + 1][row] = v.y;
            As[kq * 4 + 2][row] = v.z; As[kq * 4 + 3][row] = v.w;
        }
#pragma unroll
        for (int i = 0; i < 2; i++) {
            int f = tid + 256 * i;
            int k = f >> 4, c4 = f & 15;
            *(float4*)&Bs[k][c4 * 4] = *(const float4*)&W[(k0 + k) * HD + c4 * 4];
        }
        __syncthreads();
#pragma unroll
        for (int k = 0; k < 32; k++) {
            float4 b4 = *(float4*)&Bs[k][tx * 4];
            float4 a0 = *(float4*)&As[k][ty * 8];
            float4 a1 = *(float4*)&As[k][ty * 8 + 4];
            acc[0][0] += a0.x * b4.x; acc[0][1] += a0.x * b4.y; acc[0][2] += a0.x * b4.z; acc[0][3] += a0.x * b4.w;
            acc[1][0] += a0.y * b4.x; acc[1][1] += a0.y * b4.y; acc[1][2] += a0.y * b4.z; acc[1][3] += a0.y * b4.w;
            acc[2][0] += a0.z * b4.x; acc[2][1] += a0.z * b4.y; acc[2][2] += a0.z * b4.z; acc[2][3] += a0.z * b4.w;
            acc[3][0] += a0.w * b4.x; acc[3][1] += a0.w * b4.y; acc[3][2] += a0.w * b4.z; acc[3][3] += a0.w * b4.w;
            acc[4][0] += a1.x * b4.x; acc[4][1] += a1.x * b4.y; acc[4][2] += a1.x * b4.z; acc[4][3] += a1.x * b4.w;
            acc[5][0] += a1.y * b4.x; acc[5][1] += a1.y * b4.y; acc[5][2] += a1.y * b4.z; acc[5][3] += a1.y * b4.w;
            acc[6][0] += a1.z * b4.x; acc[6][1] += a1.z * b4.y; acc[6][2] += a1.z * b4.z; acc[6][3] += a1.z * b4.w;
            acc[7][0] += a1.w * b4.x; acc[7][1] += a1.w * b4.y; acc[7][2] += a1.w * b4.z; acc[7][3] += a1.w * b4.w;
        }
        __syncthreads();
    }

    // epilogue: feat store + el/er dots (reduce over 4 tx of each head)
    int h = tx >> 2;
    float4 al = ((const float4*)attn_l)[h * 4 + (tx & 3)];
    float4 ar = ((const float4*)attn_r)[h * 4 + (tx & 3)];
#pragma unroll
    for (int i = 0; i < 8; i++) {
        int r = rb + ty * 8 + i;
        float4 o = make_float4(acc[i][0], acc[i][1], acc[i][2], acc[i][3]);
        float lp = o.x * al.x + o.y * al.y + o.z * al.z + o.w * al.w;
        float rp = o.x * ar.x + o.y * ar.y + o.z * ar.z + o.w * ar.w;
        lp += __shfl_xor_sync(0xffffffffu, lp, 1);
        lp += __shfl_xor_sync(0xffffffffu, lp, 2);
        rp += __shfl_xor_sync(0xffffffffu, rp, 1);
        rp += __shfl_xor_sync(0xffffffffu, rp, 2);
        if (r < N_NODES) {
            g_feat[(long)r * 16 + tx] = o;
            if ((tx & 3) == 0) {
                ((float*)g_el)[r * 4 + h] = lp;
                ((float*)g_er)[r * 4 + h] = rp;
            }
        }
    }
}

// ---------------- counting sort by dst ---------------------------------------
__global__ __launch_bounds__(256) void k_hist(const int* __restrict__ dst) {
    int i = blockIdx.x * 256 + threadIdx.x;
    if (i < N_EDGES) atomicAdd(&g_cnt[dst[i]], 1);
}

__global__ __launch_bounds__(SCAN_B) void k_scan1() {
    __shared__ int sh[SCAN_B];
    int b = blockIdx.x, t = threadIdx.x;
    int i = b * SCAN_B + t;
    sh[t] = (i < N_NODES) ? g_cnt[i] : 0;
#pragma unroll
    for (int o = 1; o < SCAN_B; o <<= 1) {
        __syncthreads();
        int add = (t >= o) ? sh[t - o] : 0;
        __syncthreads();
        sh[t] += add;
    }
    __syncthreads();
    if (i < N_NODES) g_incl[i] = sh[t];
    if (t == SCAN_B - 1) g_bsum[b] = sh[t];
}

__global__ void k_scan2() {
    if (threadIdx.x == 0) {
        int run = 0;
        for (int b = 0; b < NB; b++) { g_boff[b] = run; run += g_bsum[b]; }
    }
}

__global__ void k_scan3() {
    int i = blockIdx.x * 256 + threadIdx.x;
    if (i < N_NODES) {
        int s = g_boff[i >> 10] + g_incl[i] - g_cnt[i];   // exclusive start
        g_rowptr[i] = s;
        g_cur[i] = s;
    }
    if (i == 0) g_rowptr[N_NODES] = N_EDGES;
}

__global__ __launch_bounds__(256) void k_scatter(const int* __restrict__ src,
                                                 const int* __restrict__ dst,
                                                 const int* __restrict__ et) {
    int i = blockIdx.x * 256 + threadIdx.x;
    if (i >= N_EDGES) return;
    int p = atomicAdd(&g_cur[dst[i]], 1);
    g_es[p] = make_int2(src[i], (i << 2) | et[i]);
}

// ---------------- fused softmax + aggregate: one warp per dst node -----------
__global__ __launch_bounds__(256) void k_agg(float* __restrict__ rst,
                                             float* __restrict__ out_a) {
    int d = (blockIdx.x * 256 + threadIdx.x) >> 5;
    int lane = threadIdx.x & 31;
    if (d >= N_NODES) return;
    int start = g_rowptr[d], end = g_rowptr[d + 1];
    float2* rout = (float2*)(rst + (long)d * HD);
    if (start == end) { rout[lane] = make_float2(0.f, 0.f); return; }

    const float*  elf   = (const float*)g_el;
    const float*  erf   = (const float*)g_er;
    const float*  eef   = (const float*)g_ee;
    const float2* feat2 = (const float2*)g_feat;

    // ---- pass 1: z + unnormalized aggregation; lane owns feat cols 2l..2l+1
    int h = lane >> 3;
    float erh = erf[d * 4 + h];
    float ee0 = eef[h], ee1 = eef[4 + h], ee2 = eef[8 + h];
    float z = 0.f;
    float2 acc = make_float2(0.f, 0.f);
    for (int e = start; e < end; e++) {
        int2 m = g_es[e];
        int t = m.y & 3;
        float eet = (t == 0) ? ee0 : ((t == 1) ? ee1 : ee2);
        float sc = elf[m.x * 4 + h] + erh + eet;
        sc = sc > 0.f ? sc : NEG_SLOPE * sc;
        float ev = __expf(sc);
        z += ev;
        float2 f = feat2[(long)m.x * 32 + lane];
        acc.x += f.x * ev;
        acc.y += f.y * ev;
    }
    float invz = 1.0f / z;
    rout[lane] = make_float2(acc.x * invz, acc.y * invz);

    // ---- pass 2: write a; 8 edges per iter, lane = group*4 + head
    int h2 = lane & 3, g = lane >> 2;
    float er2 = erf[d * 4 + h2];
    float f0 = eef[h2], f1 = eef[4 + h2], f2 = eef[8 + h2];
    float invz2 = __shfl_sync(0xffffffffu, invz, h2 << 3);
    for (int e0 = start; e0 < end; e0 += 8) {
        int e = e0 + g;
        if (e < end) {
            int2 m = g_es[e];
            int t = m.y & 3;
            float eet = (t == 0) ? f0 : ((t == 1) ? f1 : f2);
            float sc = elf[m.x * 4 + h2] + er2 + eet;
            sc = sc > 0.f ? sc : NEG_SLOPE * sc;
            out_a[(long)(m.y >> 2) * 4 + h2] = __expf(sc) * invz2;
        }
    }
}

// ---------------- launch ------------------------------------------------------
extern "C" void kernel_launch(void* const* d_in, const int* in_sizes, int n_in,
                              void* d_out, int out_size) {
    const float* x        = (const float*)d_in[0];
    const float* W        = (const float*)d_in[1];
    const float* W_e      = (const float*)d_in[2];
    const float* attn_l   = (const float*)d_in[3];
    const float* attn_r   = (const float*)d_in[4];
    const float* attn_e   = (const float*)d_in[5];
    const float* edge_emb = (const float*)d_in[6];
    const int*   src      = (const int*)d_in[7];
    const int*   dst      = (const int*)d_in[8];
    const int*   et       = (const int*)d_in[9];

    float* rst   = (float*)d_out;
    float* out_a = rst + (long)N_NODES * HD;

    int nb = (N_NODES + 255) / 256;
    int eb = (N_EDGES + 255) / 256;

    // fork: sort chain runs on a side stream, overlapped with k_ee + k_gemm.
    cudaStream_t s2;
    cudaEvent_t evFork, evJoin;
    cudaStreamCreateWithFlags(&s2, cudaStreamNonBlocking);
    cudaEventCreateWithFlags(&evFork, cudaEventDisableTiming);
    cudaEventCreateWithFlags(&evJoin, cudaEventDisableTiming);

    k_init<<<nb, 256>>>();
    cudaEventRecord(evFork, 0);
    cudaStreamWaitEvent(s2, evFork, 0);

    // main stream: projection GEMM (+ tiny ee)
    k_ee<<<1, 384>>>(W_e, attn_e, edge_emb);
    k_gemm<<<(N_NODES + 127) / 128, 256>>>(x, W, attn_l, attn_r);

    // side stream: counting sort by dst
    k_hist<<<eb, 256, 0, s2>>>(dst);
    k_scan1<<<NB, SCAN_B, 0, s2>>>();
    k_scan2<<<1, 32, 0, s2>>>();
    k_scan3<<<nb, 256, 0, s2>>>();
    k_scatter<<<eb, 256, 0, s2>>>(src, dst, et);
    cudaEventRecord(evJoin, s2);
    cudaStreamWaitEvent(0, evJoin, 0);

    k_agg<<<(N_NODES * 32 + 255) / 256, 256>>>(rst, out_a);

    cudaStreamDestroy(s2);
    cudaEventDestroy(evFork);
    cudaEventDestroy(evJoin);
}

// round 4
// speedup vs baseline: 1.2193x; 1.2193x over previous
#include <cuda_runtime.h>
#include <cstdint>

#define N_NODES   100000
#define N_EDGES   1600000
#define N_ETYPES  3
#define IN_FEATS  128
#define HEADS     4
#define OUT_FEATS 16
#define HD        64
#define NEG_SLOPE 0.2f
#define SCAN_B    1024
#define NB        ((N_NODES + SCAN_B - 1) / SCAN_B)   // 98

// ---------------- device scratch (static globals; no allocation) -------------
__device__ float4 g_feat[N_NODES * 16];   // [N][64] as 16 x float4 (25.6 MB)
__device__ float4 g_el[N_NODES];          // [N][4]
__device__ float4 g_er[N_NODES];          // [N][4]
__device__ float4 g_ee[N_ETYPES];         // [3][4]
__device__ int    g_cnt[N_NODES];
__device__ int    g_incl[N_NODES];
__device__ int    g_bsum[NB];
__device__ int    g_boff[NB];
__device__ int    g_rowptr[N_NODES + 1];
__device__ int    g_cur[N_NODES];
__device__ int2   g_es[N_EDGES];          // sorted: {src, orig_id*4 | etype}

// ---------------- init: zero histogram ---------------------------------------
__global__ void k_init() {
    int i = blockIdx.x * 256 + threadIdx.x;
    if (i < N_NODES) g_cnt[i] = 0;
}

// ---------------- per-etype edge term ee[t][h] -------------------------------
__global__ void k_ee(const float* __restrict__ W_e, const float* __restrict__ attn_e,
                     const float* __restrict__ edge_emb) {
    int w = threadIdx.x >> 5, lane = threadIdx.x & 31;
    if (w >= N_ETYPES * HEADS) return;
    int t = w >> 2, h = w & 3;
    float acc = 0.0f;
#pragma unroll
    for (int ei = 0; ei < 2; ei++) {
        int e = lane + ei * 32;
        float dot = 0.0f;
#pragma unroll 8
        for (int k = 0; k < 64; k++)
            dot += edge_emb[t * 64 + k] * W_e[k * 256 + h * 64 + e];
        acc += dot * attn_e[h * 64 + e];
    }
#pragma unroll
    for (int o = 16; o; o >>= 1) acc += __shfl_xor_sync(0xffffffffu, acc, o);
    if (lane == 0) ((float*)g_ee)[t * 4 + h] = acc;
}

// ---------------- counting sort: histogram ------------------------------------
__global__ __launch_bounds__(256) void k_hist(const int* __restrict__ dst) {
    int i = blockIdx.x * 256 + threadIdx.x;
    if (i < N_EDGES) atomicAdd(&g_cnt[dst[i]], 1);
}

// ---------------- GEMM: feat = x @ W  (+ fused el/er epilogue) ---------------
// 128 rows x 64 cols per block, 128 threads, 8x8 microtile.
// Per k-step: 8KB smem reads (64 cyc) vs 8192 FMA (64 cyc) -> balanced.
__global__ __launch_bounds__(128) void k_gemm(const float* __restrict__ x,
                                              const float* __restrict__ W,
                                              const float* __restrict__ attn_l,
                                              const float* __restrict__ attn_r) {
    __shared__ float As[32][132];   // transposed A tile
    __shared__ float Bs[32][64];
    int tid = threadIdx.x;
    int tx = tid & 7, ty = tid >> 3;   // tx: 8 col-groups, ty: 16 row-groups
    int rb = blockIdx.x * 128;
    float acc[8][8] = {};

    for (int k0 = 0; k0 < IN_FEATS; k0 += 32) {
#pragma unroll
        for (int i = 0; i < 8; i++) {
            int f   = tid + 128 * i;      // float4 slot 0..1023
            int row = f >> 3;             // 0..127
            int kq  = f & 7;              // k = kq*4
            float4 v = make_float4(0.f, 0.f, 0.f, 0.f);
            int gr = rb + row;
            if (gr < N_NODES) v = *(const float4*)&x[(long)gr * IN_FEATS + k0 + kq * 4];
            As[kq * 4 + 0][row] = v.x; As[kq * 4 + 1][row] = v.y;
            As[kq * 4 + 2][row] = v.z; As[kq * 4 + 3][row] = v.w;
        }
#pragma unroll
        for (int i = 0; i < 4; i++) {
            int f = tid + 128 * i;
            int k = f >> 4, c4 = f & 15;
            *(float4*)&Bs[k][c4 * 4] = *(const float4*)&W[(k0 + k) * HD + c4 * 4];
        }
        __syncthreads();
#pragma unroll
        for (int k = 0; k < 32; k++) {
            float4 a0 = *(float4*)&As[k][ty * 8];
            float4 a1 = *(float4*)&As[k][ty * 8 + 4];
            float4 b0 = *(float4*)&Bs[k][tx * 8];
            float4 b1 = *(float4*)&Bs[k][tx * 8 + 4];
            float av[8] = {a0.x, a0.y, a0.z, a0.w, a1.x, a1.y, a1.z, a1.w};
            float bv[8] = {b0.x, b0.y, b0.z, b0.w, b1.x, b1.y, b1.z, b1.w};
#pragma unroll
            for (int i = 0; i < 8; i++)
#pragma unroll
                for (int j = 0; j < 8; j++)
                    acc[i][j] += av[i] * bv[j];
        }
        __syncthreads();
    }

    // epilogue: cols tx*8..tx*8+7 all lie inside head h = tx>>1.
    int h = tx >> 1;
    int co = (tx & 1) * 8;              // col offset within head
    float al[8], ar[8];
    *(float4*)&al[0] = *(const float4*)&attn_l[h * 16 + co];
    *(float4*)&al[4] = *(const float4*)&attn_l[h * 16 + co + 4];
    *(float4*)&ar[0] = *(const float4*)&attn_r[h * 16 + co];
    *(float4*)&ar[4] = *(const float4*)&attn_r[h * 16 + co + 4];
#pragma unroll
    for (int i = 0; i < 8; i++) {
        int r = rb + ty * 8 + i;
        float lp = 0.f, rp = 0.f;
#pragma unroll
        for (int j = 0; j < 8; j++) { lp += acc[i][j] * al[j]; rp += acc[i][j] * ar[j]; }
        lp += __shfl_xor_sync(0xffffffffu, lp, 1);   // combine the two halves of the head
        rp += __shfl_xor_sync(0xffffffffu, rp, 1);
        if (r < N_NODES) {
            float* fr = (float*)&g_feat[(long)r * 16];
            *(float4*)&fr[tx * 8]     = make_float4(acc[i][0], acc[i][1], acc[i][2], acc[i][3]);
            *(float4*)&fr[tx * 8 + 4] = make_float4(acc[i][4], acc[i][5], acc[i][6], acc[i][7]);
            if ((tx & 1) == 0) {
                ((float*)g_el)[r * 4 + h] = lp;
                ((float*)g_er)[r * 4 + h] = rp;
            }
        }
    }
}

// ---------------- counting sort: scan + scatter -------------------------------
__global__ __launch_bounds__(SCAN_B) void k_scan1() {
    __shared__ int sh[SCAN_B];
    int b = blockIdx.x, t = threadIdx.x;
    int i = b * SCAN_B + t;
    sh[t] = (i < N_NODES) ? g_cnt[i] : 0;
#pragma unroll
    for (int o = 1; o < SCAN_B; o <<= 1) {
        __syncthreads();
        int add = (t >= o) ? sh[t - o] : 0;
        __syncthreads();
        sh[t] += add;
    }
    __syncthreads();
    if (i < N_NODES) g_incl[i] = sh[t];
    if (t == SCAN_B - 1) g_bsum[b] = sh[t];
}

__global__ void k_scan2() {
    if (threadIdx.x == 0) {
        int run = 0;
        for (int b = 0; b < NB; b++) { g_boff[b] = run; run += g_bsum[b]; }
    }
}

__global__ void k_scan3() {
    int i = blockIdx.x * 256 + threadIdx.x;
    if (i < N_NODES) {
        int s = g_boff[i >> 10] + g_incl[i] - g_cnt[i];
        g_rowptr[i] = s;
        g_cur[i] = s;
    }
    if (i == 0) g_rowptr[N_NODES] = N_EDGES;
}

__global__ __launch_bounds__(256) void k_scatter(const int* __restrict__ src,
                                                 const int* __restrict__ dst,
                                                 const int* __restrict__ et) {
    int i = blockIdx.x * 256 + threadIdx.x;
    if (i >= N_EDGES) return;
    int p = atomicAdd(&g_cur[dst[i]], 1);
    g_es[p] = make_int2(src[i], (i << 2) | et[i]);
}

// ---------------- fused softmax + aggregate: one warp per dst node -----------
__global__ __launch_bounds__(256) void k_agg(float* __restrict__ rst,
                                             float* __restrict__ out_a) {
    int d = (blockIdx.x * 256 + threadIdx.x) >> 5;
    int lane = threadIdx.x & 31;
    if (d >= N_NODES) return;
    int start = g_rowptr[d], end = g_rowptr[d + 1];
    float2* rout = (float2*)(rst + (long)d * HD);
    if (start == end) { rout[lane] = make_float2(0.f, 0.f); return; }

    const float*  elf   = (const float*)g_el;
    const float*  erf   = (const float*)g_er;
    const float*  eef   = (const float*)g_ee;
    const float2* feat2 = (const float2*)g_feat;

    // ---- pass 1: z + unnormalized aggregation; lane owns feat cols 2l..2l+1
    int h = lane >> 3;
    float erh = erf[d * 4 + h];
    float ee0 = eef[h], ee1 = eef[4 + h], ee2 = eef[8 + h];
    float z = 0.f;
    float2 acc = make_float2(0.f, 0.f);
    for (int e = start; e < end; e++) {
        int2 m = g_es[e];
        int t = m.y & 3;
        float eet = (t == 0) ? ee0 : ((t == 1) ? ee1 : ee2);
        float sc = elf[m.x * 4 + h] + erh + eet;
        sc = sc > 0.f ? sc : NEG_SLOPE * sc;
        float ev = __expf(sc);
        z += ev;
        float2 f = feat2[(long)m.x * 32 + lane];
        acc.x += f.x * ev;
        acc.y += f.y * ev;
    }
    float invz = 1.0f / z;
    rout[lane] = make_float2(acc.x * invz, acc.y * invz);

    // ---- pass 2: write a; 8 edges per iter, lane = group*4 + head
    int h2 = lane & 3, g = lane >> 2;
    float er2 = erf[d * 4 + h2];
    float f0 = eef[h2], f1 = eef[4 + h2], f2 = eef[8 + h2];
    float invz2 = __shfl_sync(0xffffffffu, invz, h2 << 3);
    for (int e0 = start; e0 < end; e0 += 8) {
        int e = e0 + g;
        if (e < end) {
            int2 m = g_es[e];
            int t = m.y & 3;
            float eet = (t == 0) ? f0 : ((t == 1) ? f1 : f2);
            float sc = elf[m.x * 4 + h2] + er2 + eet;
            sc = sc > 0.f ? sc : NEG_SLOPE * sc;
            out_a[(long)(m.y >> 2) * 4 + h2] = __expf(sc) * invz2;
        }
    }
}

// ---------------- launch ------------------------------------------------------
extern "C" void kernel_launch(void* const* d_in, const int* in_sizes, int n_in,
                              void* d_out, int out_size) {
    const float* x        = (const float*)d_in[0];
    const float* W        = (const float*)d_in[1];
    const float* W_e      = (const float*)d_in[2];
    const float* attn_l   = (const float*)d_in[3];
    const float* attn_r   = (const float*)d_in[4];
    const float* attn_e   = (const float*)d_in[5];
    const float* edge_emb = (const float*)d_in[6];
    const int*   src      = (const int*)d_in[7];
    const int*   dst      = (const int*)d_in[8];
    const int*   et       = (const int*)d_in[9];

    float* rst   = (float*)d_out;
    float* out_a = rst + (long)N_NODES * HD;

    int nb = (N_NODES + 255) / 256;
    int eb = (N_EDGES + 255) / 256;

    // single stream, serial. k_gemm placed 4th so the ncu slot profiles it.
    k_init<<<nb, 256>>>();
    k_ee<<<1, 384>>>(W_e, attn_e, edge_emb);
    k_hist<<<eb, 256>>>(dst);
    k_gemm<<<(N_NODES + 127) / 128, 128>>>(x, W, attn_l, attn_r);
    k_scan1<<<NB, SCAN_B>>>();
    k_scan2<<<1, 32>>>();
    k_scan3<<<nb, 256>>>();
    k_scatter<<<eb, 256>>>(src, dst, et);
    k_agg<<<(N_NODES * 32 + 255) / 256, 256>>>(rst, out_a);
}

// round 5
// speedup vs baseline: 1.3117x; 1.0758x over previous
#include <cuda_runtime.h>
#include <cstdint>

#define N_NODES   100000
#define N_EDGES   1600000
#define N_ETYPES  3
#define IN_FEATS  128
#define HEADS     4
#define OUT_FEATS 16
#define HD        64
#define NEG_SLOPE 0.2f
#define SCAN_B    1024
#define NB        ((N_NODES + SCAN_B - 1) / SCAN_B)   // 98

// ---------------- device scratch (static globals; no allocation) -------------
__device__ float4 g_feat[N_NODES * 16];   // [N][64] as 16 x float4 (25.6 MB)
__device__ float4 g_el[N_NODES];          // [N][4]
__device__ float4 g_er[N_NODES];          // [N][4]
__device__ float4 g_ee[N_ETYPES];         // [3][4]
__device__ int    g_cnt[N_NODES];
__device__ int    g_incl[N_NODES];
__device__ int    g_bsum[NB];
__device__ int    g_boff[NB];
__device__ int    g_rowptr[N_NODES + 1];
__device__ int    g_cur[N_NODES];
__device__ int2   g_es[N_EDGES];          // sorted: {src, orig_id*4 | etype}

// ---------------- init: zero histogram ---------------------------------------
__global__ void k_init() {
    int i = blockIdx.x * 256 + threadIdx.x;
    if (i < N_NODES) g_cnt[i] = 0;
}

// ---------------- per-etype edge term ee[t][h] -------------------------------
__global__ void k_ee(const float* __restrict__ W_e, const float* __restrict__ attn_e,
                     const float* __restrict__ edge_emb) {
    int w = threadIdx.x >> 5, lane = threadIdx.x & 31;
    if (w >= N_ETYPES * HEADS) return;
    int t = w >> 2, h = w & 3;
    float acc = 0.0f;
#pragma unroll
    for (int ei = 0; ei < 2; ei++) {
        int e = lane + ei * 32;
        float dot = 0.0f;
#pragma unroll 8
        for (int k = 0; k < 64; k++)
            dot += edge_emb[t * 64 + k] * W_e[k * 256 + h * 64 + e];
        acc += dot * attn_e[h * 64 + e];
    }
#pragma unroll
    for (int o = 16; o; o >>= 1) acc += __shfl_xor_sync(0xffffffffu, acc, o);
    if (lane == 0) ((float*)g_ee)[t * 4 + h] = acc;
}

// ---------------- counting sort: histogram ------------------------------------
__global__ __launch_bounds__(256) void k_hist(const int* __restrict__ dst) {
    int i = blockIdx.x * 256 + threadIdx.x;
    if (i < N_EDGES) atomicAdd(&g_cnt[dst[i]], 1);
}

// ---------------- GEMM: feat = x @ W  (+ fused el/er epilogue) ---------------
// 128 rows x 64 cols per block, 128 threads, 8x8 microtile.
__global__ __launch_bounds__(128) void k_gemm(const float* __restrict__ x,
                                              const float* __restrict__ W,
                                              const float* __restrict__ attn_l,
                                              const float* __restrict__ attn_r) {
    __shared__ float As[32][132];   // transposed A tile
    __shared__ float Bs[32][64];
    int tid = threadIdx.x;
    int tx = tid & 7, ty = tid >> 3;
    int rb = blockIdx.x * 128;
    float acc[8][8] = {};

    for (int k0 = 0; k0 < IN_FEATS; k0 += 32) {
#pragma unroll
        for (int i = 0; i < 8; i++) {
            int f   = tid + 128 * i;
            int row = f >> 3;
            int kq  = f & 7;
            float4 v = make_float4(0.f, 0.f, 0.f, 0.f);
            int gr = rb + row;
            if (gr < N_NODES) v = *(const float4*)&x[(long)gr * IN_FEATS + k0 + kq * 4];
            As[kq * 4 + 0][row] = v.x; As[kq * 4 + 1][row] = v.y;
            As[kq * 4 + 2][row] = v.z; As[kq * 4 + 3][row] = v.w;
        }
#pragma unroll
        for (int i = 0; i < 4; i++) {
            int f = tid + 128 * i;
            int k = f >> 4, c4 = f & 15;
            *(float4*)&Bs[k][c4 * 4] = *(const float4*)&W[(k0 + k) * HD + c4 * 4];
        }
        __syncthreads();
#pragma unroll
        for (int k = 0; k < 32; k++) {
            float4 a0 = *(float4*)&As[k][ty * 8];
            float4 a1 = *(float4*)&As[k][ty * 8 + 4];
            float4 b0 = *(float4*)&Bs[k][tx * 8];
            float4 b1 = *(float4*)&Bs[k][tx * 8 + 4];
            float av[8] = {a0.x, a0.y, a0.z, a0.w, a1.x, a1.y, a1.z, a1.w};
            float bv[8] = {b0.x, b0.y, b0.z, b0.w, b1.x, b1.y, b1.z, b1.w};
#pragma unroll
            for (int i = 0; i < 8; i++)
#pragma unroll
                for (int j = 0; j < 8; j++)
                    acc[i][j] += av[i] * bv[j];
        }
        __syncthreads();
    }

    int h = tx >> 1;
    int co = (tx & 1) * 8;
    float al[8], ar[8];
    *(float4*)&al[0] = *(const float4*)&attn_l[h * 16 + co];
    *(float4*)&al[4] = *(const float4*)&attn_l[h * 16 + co + 4];
    *(float4*)&ar[0] = *(const float4*)&attn_r[h * 16 + co];
    *(float4*)&ar[4] = *(const float4*)&attn_r[h * 16 + co + 4];
#pragma unroll
    for (int i = 0; i < 8; i++) {
        int r = rb + ty * 8 + i;
        float lp = 0.f, rp = 0.f;
#pragma unroll
        for (int j = 0; j < 8; j++) { lp += acc[i][j] * al[j]; rp += acc[i][j] * ar[j]; }
        lp += __shfl_xor_sync(0xffffffffu, lp, 1);
        rp += __shfl_xor_sync(0xffffffffu, rp, 1);
        if (r < N_NODES) {
            float* fr = (float*)&g_feat[(long)r * 16];
            *(float4*)&fr[tx * 8]     = make_float4(acc[i][0], acc[i][1], acc[i][2], acc[i][3]);
            *(float4*)&fr[tx * 8 + 4] = make_float4(acc[i][4], acc[i][5], acc[i][6], acc[i][7]);
            if ((tx & 1) == 0) {
                ((float*)g_el)[r * 4 + h] = lp;
                ((float*)g_er)[r * 4 + h] = rp;
            }
        }
    }
}

// ---------------- counting sort: scan + scatter -------------------------------
__global__ __launch_bounds__(SCAN_B) void k_scan1() {
    __shared__ int sh[SCAN_B];
    int b = blockIdx.x, t = threadIdx.x;
    int i = b * SCAN_B + t;
    sh[t] = (i < N_NODES) ? g_cnt[i] : 0;
#pragma unroll
    for (int o = 1; o < SCAN_B; o <<= 1) {
        __syncthreads();
        int add = (t >= o) ? sh[t - o] : 0;
        __syncthreads();
        sh[t] += add;
    }
    __syncthreads();
    if (i < N_NODES) g_incl[i] = sh[t];
    if (t == SCAN_B - 1) g_bsum[b] = sh[t];
}

__global__ void k_scan2() {
    if (threadIdx.x == 0) {
        int run = 0;
        for (int b = 0; b < NB; b++) { g_boff[b] = run; run += g_bsum[b]; }
    }
}

__global__ void k_scan3() {
    int i = blockIdx.x * 256 + threadIdx.x;
    if (i < N_NODES) {
        int s = g_boff[i >> 10] + g_incl[i] - g_cnt[i];
        g_rowptr[i] = s;
        g_cur[i] = s;
    }
    if (i == 0) g_rowptr[N_NODES] = N_EDGES;
}

__global__ __launch_bounds__(256) void k_scatter(const int* __restrict__ src,
                                                 const int* __restrict__ dst,
                                                 const int* __restrict__ et) {
    int i = blockIdx.x * 256 + threadIdx.x;
    if (i >= N_EDGES) return;
    int p = atomicAdd(&g_cur[dst[i]], 1);
    g_es[p] = make_int2(src[i], (i << 2) | et[i]);
}

// ---------------- fused softmax + aggregate: one warp per dst node -----------
// pass 1: two 16-lane halves each own one in-flight edge (float4/lane covers
// the 64-col row); next edge record prefetched one iteration ahead.
__global__ __launch_bounds__(256) void k_agg(float* __restrict__ rst,
                                             float* __restrict__ out_a) {
    int d = (blockIdx.x * 256 + threadIdx.x) >> 5;
    int lane = threadIdx.x & 31;
    if (d >= N_NODES) return;
    int start = g_rowptr[d], end = g_rowptr[d + 1];
    float4* rout4 = (float4*)(rst + (long)d * HD);
    int sl = lane & 15, half = lane >> 4;
    if (start == end) {
        if (half == 0) rout4[sl] = make_float4(0.f, 0.f, 0.f, 0.f);
        return;
    }

    const float* elf = (const float*)g_el;
    const float* erf = (const float*)g_er;
    const float* eef = (const float*)g_ee;

    int h = sl >> 2;                      // head owning float4-col sl
    float erh = erf[d * 4 + h];
    float ee0 = eef[h], ee1 = eef[4 + h], ee2 = eef[8 + h];

    float z = 0.f;
    float4 acc = make_float4(0.f, 0.f, 0.f, 0.f);
    int e = start + half;
    int2 m = (e < end) ? g_es[e] : make_int2(0, 0);
    for (; e < end; e += 2) {
        int2 mn = m;
        if (e + 2 < end) mn = g_es[e + 2];         // prefetch next
        int t = m.y & 3;
        float eet = (t == 0) ? ee0 : ((t == 1) ? ee1 : ee2);
        float sc = elf[m.x * 4 + h] + erh + eet;
        sc = sc > 0.f ? sc : NEG_SLOPE * sc;
        float ev = __expf(sc);
        float4 f = g_feat[(long)m.x * 16 + sl];
        z += ev;
        acc.x += f.x * ev; acc.y += f.y * ev;
        acc.z += f.z * ev; acc.w += f.w * ev;
        m = mn;
    }
    // combine the two halves
    z     += __shfl_xor_sync(0xffffffffu, z, 16);
    acc.x += __shfl_xor_sync(0xffffffffu, acc.x, 16);
    acc.y += __shfl_xor_sync(0xffffffffu, acc.y, 16);
    acc.z += __shfl_xor_sync(0xffffffffu, acc.z, 16);
    acc.w += __shfl_xor_sync(0xffffffffu, acc.w, 16);
    float invz = 1.0f / z;
    if (half == 0)
        rout4[sl] = make_float4(acc.x * invz, acc.y * invz, acc.z * invz, acc.w * invz);

    // ---- pass 2: write a; 8 edges per iter, lane = group*4 + head
    int h2 = lane & 3, g = lane >> 2;
    float er2 = erf[d * 4 + h2];
    float f0 = eef[h2], f1 = eef[4 + h2], f2 = eef[8 + h2];
    float invz2 = __shfl_sync(0xffffffffu, invz, h2 * 4);   // lane with sl=h2*4 holds head h2
    for (int e0 = start; e0 < end; e0 += 8) {
        int ei = e0 + g;
        if (ei < end) {
            int2 me = g_es[ei];
            int t = me.y & 3;
            float eet = (t == 0) ? f0 : ((t == 1) ? f1 : f2);
            float sc = elf[me.x * 4 + h2] + er2 + eet;
            sc = sc > 0.f ? sc : NEG_SLOPE * sc;
            __stcs(&out_a[(long)(me.y >> 2) * 4 + h2], __expf(sc) * invz2);
        }
    }
}

// ---------------- launch ------------------------------------------------------
extern "C" void kernel_launch(void* const* d_in, const int* in_sizes, int n_in,
                              void* d_out, int out_size) {
    const float* x        = (const float*)d_in[0];
    const float* W        = (const float*)d_in[1];
    const float* W_e      = (const float*)d_in[2];
    const float* attn_l   = (const float*)d_in[3];
    const float* attn_r   = (const float*)d_in[4];
    const float* attn_e   = (const float*)d_in[5];
    const float* edge_emb = (const float*)d_in[6];
    const int*   src      = (const int*)d_in[7];
    const int*   dst      = (const int*)d_in[8];
    const int*   et       = (const int*)d_in[9];

    float* rst   = (float*)d_out;
    float* out_a = rst + (long)N_NODES * HD;

    int nb = (N_NODES + 255) / 256;
    int eb = (N_EDGES + 255) / 256;

    k_init<<<nb, 256>>>();
    k_ee<<<1, 384>>>(W_e, attn_e, edge_emb);
    k_hist<<<eb, 256>>>(dst);
    k_gemm<<<(N_NODES + 127) / 128, 128>>>(x, W, attn_l, attn_r);
    k_scan1<<<NB, SCAN_B>>>();
    k_scan2<<<1, 32>>>();
    k_scan3<<<nb, 256>>>();
    k_scatter<<<eb, 256>>>(src, dst, et);
    k_agg<<<(N_NODES * 32 + 255) / 256, 256>>>(rst, out_a);
}